// round 13
// baseline (speedup 1.0000x reference)
#include <cuda_runtime.h>
#include <cstdint>
#include <math.h>

// ---------------------------------------------------------------------------
// R22SDF fixed-point FFT, N=256 complex (512 real in), 16384 rows.
// out = float32[rows][257] = real part of the reference complex output.
// R13: complex values carried as packed 64-bit (f32x2) registers end-to-end;
// all packed asm uses "l" constraints to eliminate pack/unpack MOV friction.
// Same math as R12 -> bit-exact vs reference.
// ---------------------------------------------------------------------------

#define MAX_ROWS 16384

typedef unsigned long long P;   // packed (float x, float y): x = low word

// ===== compile-time quantized tables ========================================

struct alignas(8) C2 { float x, y; };

constexpr double PI_D = 3.141592653589793238462643383279502884;

constexpr double tsin(double x)
{
    double term = x, sum = x;
    for (int i = 1; i < 26; ++i) {
        term *= -(x * x) / double((2 * i) * (2 * i + 1));
        sum += term;
    }
    return sum;
}
constexpr double tcos(double x)
{
    double term = 1.0, sum = 1.0;
    for (int i = 1; i < 26; ++i) {
        term *= -(x * x) / double((2 * i - 1) * (2 * i));
        sum += term;
    }
    return sum;
}
// rint(float(v)*16)/16 — no ties occur (margin >= 5e-3), so half-away == RNE
constexpr float q16(double v)
{
    float s = (float)v * 16.0f;
    long r = (s >= 0.0f) ? (long)(s + 0.5f) : -(long)(-s + 0.5f);
    return (float)r * 0.0625f;
}
constexpr float q4(double v)
{
    float s = (float)v * 4.0f;
    long r = (s >= 0.0f) ? (long)(s + 0.5f) : -(long)(-s + 0.5f);
    return (float)r * 0.25f;
}
constexpr C2 wN(int nk, double Nv)
{
    double ang = -2.0 * PI_D * (double)nk / Nv;
    float cf = q16(tcos(ang)), sf = q16(tsin(ang));
    if (cf ==  1.0f) return {  1.0f, 0.0f};
    if (cf == -1.0f) return {-1.0f, 0.0f};
    if (sf ==  1.0f) return { 0.0f, 1.0f};
    if (sf == -1.0f) return { 0.0f,-1.0f};
    return {cf, sf};
}
constexpr int qm(int q) { return q == 1 ? 2 : (q == 2 ? 1 : 3); }

// ext2[k] = EXTRA[k] / 2 for k in [0,128]  (folds the 0.5 of x_even/x_odd)
struct alignas(16) Tables { C2 tw0[256]; C2 tw1[64]; C2 tw2[16]; C2 ext2[132]; };

constexpr Tables build_tables()
{
    Tables t{};
    for (int i = 0; i < 256; ++i) {
        int q = i >> 6, r = i & 63;
        t.tw0[i] = (q == 0) ? C2{1.0f, 0.0f} : wN(r * qm(q), 256.0);
    }
    for (int b = 0; b < 64; ++b) {
        int q = b >> 4, r = b & 15;
        t.tw1[b] = (q == 0) ? C2{1.0f, 0.0f} : wN(r * qm(q), 64.0);
    }
    for (int b = 0; b < 16; ++b) {
        int q = b >> 2, r = b & 3;
        t.tw2[b] = (q == 0) ? C2{1.0f, 0.0f} : wN(r * qm(q), 16.0);
    }
    for (int k = 0; k <= 128; ++k) {
        double ang = -PI_D * (double)k / 256.0;
        t.ext2[k] = C2{q4(tcos(ang)) * 0.5f, q4(tsin(ang)) * 0.5f};
    }
    return t;
}

__device__ constexpr Tables TBL = build_tables();

// packed constant from two floats (x = low word)
constexpr P pconst(float x, float y)
{
    return ((P)__builtin_bit_cast(unsigned int, y) << 32)
         |  (P)__builtin_bit_cast(unsigned int, x);
}

#define MAGIC   12582912.0f     // 2^23 + 2^22
#define MAGLO   12582784.0f     // MAGIC - 128
#define MAGHI   12583039.0f     // MAGIC + 127

constexpr P M2     = pconst(MAGIC, MAGIC);
constexpr P NEG1   = pconst(-1.0f, -1.0f);
constexpr P S1024  = pconst(1024.0f, 1024.0f);
constexpr P R_1    = pconst(1.0f, 1.0f);
constexpr P D_1    = pconst(-MAGIC, -MAGIC);
constexpr P R_h    = pconst(0.5f, 0.5f);
constexpr P D_h    = pconst(-MAGIC * 0.5f, -MAGIC * 0.5f);
constexpr P R_q    = pconst(0.25f, 0.25f);
constexpr P D_q    = pconst(-MAGIC * 0.25f, -MAGIC * 0.25f);
constexpr P R_64   = pconst(1.0f/64.0f, 1.0f/64.0f);
constexpr P D_64   = pconst(-MAGIC/64.0f, -MAGIC/64.0f);

// ===== packed helpers ("l" constraints -> no pack/unpack movs) ================

__device__ __forceinline__ P pk(float x, float y)
{
    P r;
    asm("mov.b64 %0, {%1,%2};" : "=l"(r) : "f"(x), "f"(y));
    return r;
}
__device__ __forceinline__ void unpk(P p, float& x, float& y)
{
    asm("mov.b64 {%0,%1}, %2;" : "=f"(x), "=f"(y) : "l"(p));
}
__device__ __forceinline__ P padd(P a, P b)
{
    P r;
    asm("add.rn.f32x2 %0, %1, %2;" : "=l"(r) : "l"(a), "l"(b));
    return r;
}
__device__ __forceinline__ P padd_rm(P a, P b)
{
    P r;
    asm("add.rm.f32x2 %0, %1, %2;" : "=l"(r) : "l"(a), "l"(b));
    return r;
}
__device__ __forceinline__ P pmul(P a, P b)
{
    P r;
    asm("mul.rn.f32x2 %0, %1, %2;" : "=l"(r) : "l"(a), "l"(b));
    return r;
}
__device__ __forceinline__ P pfma(P a, P b, P c)
{
    P r;
    asm("fma.rn.f32x2 %0, %1, %2, %3;" : "=l"(r) : "l"(a), "l"(b), "l"(c));
    return r;
}

// ===== math helpers ===========================================================

// quant: t = rm(u + M); clamp t to [M-128, M+127]; out = (t - M) * ratio.
__device__ __forceinline__ P qz2(P u, P ratio, P negMr)
{
    P t = padd_rm(u, M2);
    float x, y;
    unpk(t, x, y);
    x = fminf(fmaxf(x, MAGLO), MAGHI);
    y = fminf(fmaxf(y, MAGLO), MAGHI);
    return pfma(pk(x, y), ratio, negMr);
}

__device__ __forceinline__ P cmulw(P a, P w)
{
    float ax, ay, wx, wy;
    unpk(a, ax, ay);
    unpk(w, wx, wy);
    return pk(fmaf(ax, wx, -(ay * wy)), fmaf(ax, wy, ay * wx));
}

__device__ __forceinline__ P rot_mj(P a)   // a * (-i)
{
    float x, y;
    unpk(a, x, y);
    return pk(y, -x);
}

__device__ __forceinline__ void bfly(P& a, P& b)
{
    P t = a;
    a = padd(t, b);
    b = pfma(b, NEG1, t);
}

template <int BIT>
__device__ __forceinline__ void shfl_stage(P (&v)[8])
{
    float sg = (threadIdx.x & BIT) ? -1.0f : 1.0f;
    P sg2 = pk(sg, sg);
#pragma unroll
    for (int j = 0; j < 8; ++j) {
        float x, y;
        unpk(v[j], x, y);
        float bx = __shfl_xor_sync(0xffffffffu, x, BIT);
        float by = __shfl_xor_sync(0xffffffffu, y, BIT);
        v[j] = pfma(v[j], sg2, pk(bx, by));
    }
}

__device__ __forceinline__ void quant8(P (&v)[8], P ratio, P negMr)
{
#pragma unroll
    for (int j = 0; j < 8; ++j) v[j] = qz2(v[j], ratio, negMr);
}

// ===== main kernel =============================================================

__global__ void __launch_bounds__(256)
r22sdf_kernel(const float* __restrict__ xin, float* __restrict__ outf, int rows)
{
    __shared__ P sbuf[8][256];
    const int warp = threadIdx.x >> 5;
    const int lane = threadIdx.x & 31;
    const int row  = (blockIdx.x << 3) + warp;
    if (row >= rows) return;

    const P* tw0 = reinterpret_cast<const P*>(TBL.tw0);
    const P* tw1 = reinterpret_cast<const P*>(TBL.tw1);
    const ulonglong2* tw2v = reinterpret_cast<const ulonglong2*>(TBL.tw2);
    const P* ex2 = reinterpret_cast<const P*>(TBL.ext2);

    // ---- load RAW complex pairs directly as packed 64-bit -------------------
    const P* xr = reinterpret_cast<const P*>(xin) + (size_t)row * 256;
    P v[8];
#pragma unroll
    for (int j = 0; j < 8; ++j)
        v[j] = xr[lane + 32 * j];

    // ---- stage 1 on raw values (pow2 scale commutes with rn add) ------------
#pragma unroll
    for (int j = 0; j < 4; ++j) bfly(v[j], v[j + 4]);
    v[6] = rot_mj(v[6]);
    v[7] = rot_mj(v[7]);
#pragma unroll
    for (int j = 0; j < 8; ++j)                  // scale to q64: * (16*64)
        v[j] = qz2(pmul(v[j], S1024), R_1, D_1); // 64 -> 64

    // ---- stage 2: stride 64; TWIDDLE row 0; s=64 -----------------------------
    // TW0[i]: i>>6 = j>>1, so j=0,1 sit in the identity quarter -> skip cmul.
    bfly(v[0], v[2]); bfly(v[1], v[3]); bfly(v[4], v[6]); bfly(v[5], v[7]);
    {
        P wA = __ldg(&tw0[lane +  64]);
        P wB = __ldg(&tw0[lane +  96]);
        P wC = __ldg(&tw0[lane + 128]);
        P wD = __ldg(&tw0[lane + 160]);
        P wE = __ldg(&tw0[lane + 192]);
        P wF = __ldg(&tw0[lane + 224]);
        v[2] = cmulw(v[2], wA); v[3] = cmulw(v[3], wB);
        v[4] = cmulw(v[4], wC); v[5] = cmulw(v[5], wD);
        v[6] = cmulw(v[6], wE); v[7] = cmulw(v[7], wF);
    }
    quant8(v, R_h, D_h);                        // 64 -> 32

    // ---- stage 3: stride 32; trivial -i; s=32 --------------------------------
    bfly(v[0], v[1]); bfly(v[2], v[3]); bfly(v[4], v[5]); bfly(v[6], v[7]);
    if (lane >= 16) {
        v[1] = rot_mj(v[1]); v[3] = rot_mj(v[3]);
        v[5] = rot_mj(v[5]); v[7] = rot_mj(v[7]);
    }
    quant8(v, R_1, D_1);                        // 32 -> 32

    // ---- stage 4: stride 16 (shfl); TWIDDLE row 1 = f(i&63); s=32 ------------
    shfl_stage<16>(v);
    {
        P wa = __ldg(&tw1[lane]);               // j even
        P wb = __ldg(&tw1[lane + 32]);          // j odd
        v[0] = cmulw(v[0], wa); v[1] = cmulw(v[1], wb);
        v[2] = cmulw(v[2], wa); v[3] = cmulw(v[3], wb);
        v[4] = cmulw(v[4], wa); v[5] = cmulw(v[5], wb);
        v[6] = cmulw(v[6], wa); v[7] = cmulw(v[7], wb);
    }
    quant8(v, R_q, D_q);                        // 32 -> 8

    // ---- stage 5: stride 8 (shfl); trivial -i on (i&15)>=12; s=8 -------------
    shfl_stage<8>(v);
    if ((lane & 15) >= 12) {
#pragma unroll
        for (int j = 0; j < 8; ++j) v[j] = rot_mj(v[j]);
    }
    quant8(v, R_1, D_1);                        // 8 -> 8

    // ---- transpose: layout A (i = lane+32j) -> layout B (i = 8*lane+e) -------
    P* s = sbuf[warp];
#pragma unroll
    for (int j = 0; j < 8; ++j)
        s[(lane ^ j) + 32 * j] = v[j];
    __syncwarp();
    P w[8];
    {
        const int base = 8 * lane;
        const int q = lane >> 2;
#pragma unroll
        for (int e = 0; e < 8; ++e)
            w[e] = s[base + (e ^ q)];
    }

    // ---- stage 6: stride 4 (intra); TWIDDLE row 2 = f(i&15); s=8 --------------
    bfly(w[0], w[4]); bfly(w[1], w[5]); bfly(w[2], w[6]); bfly(w[3], w[7]);
    {
        const int b4 = 4 * (lane & 1);
        ulonglong2 t0 = __ldg(&tw2v[b4 + 0]);
        ulonglong2 t1 = __ldg(&tw2v[b4 + 1]);
        ulonglong2 t2 = __ldg(&tw2v[b4 + 2]);
        ulonglong2 t3 = __ldg(&tw2v[b4 + 3]);
        w[0] = cmulw(w[0], t0.x); w[1] = cmulw(w[1], t0.y);
        w[2] = cmulw(w[2], t1.x); w[3] = cmulw(w[3], t1.y);
        w[4] = cmulw(w[4], t2.x); w[5] = cmulw(w[5], t2.y);
        w[6] = cmulw(w[6], t3.x); w[7] = cmulw(w[7], t3.y);
    }
    quant8(w, R_h, D_h);                        // 8 -> 4

    // ---- stage 7: stride 2 (intra); trivial -i on e in {3,7}; s=4 -------------
    bfly(w[0], w[2]); bfly(w[1], w[3]); bfly(w[4], w[6]); bfly(w[5], w[7]);
    w[3] = rot_mj(w[3]);
    w[7] = rot_mj(w[7]);
    quant8(w, R_1, D_1);                        // 4 -> 4

    // ---- stage 8: stride 1 (intra); no twiddle, no quant -----------------------
    bfly(w[0], w[1]); bfly(w[2], w[3]); bfly(w[4], w[5]); bfly(w[6], w[7]);

    // ---- bit-reversed store: i = 8*lane+e -> p = 32*rev3(e) + rev5(lane) -------
    __syncwarp();   // all transpose reads done before overwriting
    {
        const int r5 = (int)(__brev((unsigned)lane) >> 27);
        static const int rev3[8] = {0, 4, 2, 6, 1, 5, 3, 7};
#pragma unroll
        for (int e = 0; e < 8; ++e)
            s[(r5 ^ rev3[e]) + 32 * rev3[e]] = w[e];   // phys = p ^ (p>>5)
    }
    __syncwarp();

    // ---- post-combine via conjugate symmetry -----------------------------------
    // For pair (k, 256-k):  y(k)     = 0.5*A + ex2*B + ey2*C
    //                       y(256-k) = A - y(k)
    // A = ax+bx, B = ay+by, C = ax-bx; out = clip(floor(y), -128,127)/64.
    float* orow = outf + (size_t)row * 257;
#pragma unroll
    for (int j = 0; j < 4; ++j) {
        int k   = lane + 32 * j;                 // 0..127
        int e1  = (lane ^ j) + 32 * j;           // k ^ (k>>5)
        int km  = (256 - k) & 255;
        int e2  = km ^ (km >> 5);
        P a = s[e1];
        P b = s[e2];
        float ax, ay, bx, by, ex, ey, A, B;
        unpk(a, ax, ay);
        unpk(b, bx, by);
        unpk(__ldg(&ex2[k]), ex, ey);
        unpk(padd(a, b), A, B);
        float C  = ax - bx;
        float y  = fmaf(ey, C, fmaf(ex, B, 0.5f * A));
        float y2 = A - y;                        // exact (dyadic, small)
        float qx, qy;
        unpk(qz2(pk(y, y2), R_64, D_64), qx, qy);
        orow[k]       = qx;
        orow[256 - k] = qy;
    }
    if (lane == 0) {     // k = 128: a = b = s[132], ex2=0, C=0 -> y = a.x
        float ax, ay;
        unpk(s[132], ax, ay);
        float t = __fadd_rd(ax, MAGIC);
        t = fminf(fmaxf(t, MAGLO), MAGHI);
        orow[128] = fmaf(t, 1.0f/64.0f, -(MAGIC * (1.0f/64.0f)));
    }
}

// ===== launch ===================================================================

extern "C" void kernel_launch(void* const* d_in, const int* in_sizes, int n_in,
                              void* d_out, int out_size)
{
    const float* x = (const float*)d_in[0];

    int rows_in  = in_sizes[0] / 512;
    int rows_out = out_size / 257;
    int rows = rows_in < rows_out ? rows_in : rows_out;
    if (rows > MAX_ROWS) rows = MAX_ROWS;
    if (rows <= 0) return;

    r22sdf_kernel<<<(rows + 7) / 8, 256>>>(x, (float*)d_out, rows);
}